// round 15
// baseline (speedup 1.0000x reference)
#include <cuda_runtime.h>
#include <cuda_bf16.h>
#include <math.h>
#include <stdint.h>

#define BB 2048
#define SS 200
#define DD 192
#define H1 64
#define H2 32
#define NT 256

typedef unsigned long long ull;

// ---- smem layout (float idx) ----
#define SM_A0  0                        // rows 0-127, 256B/row = 8192 f
#define SM_A1  8192                     // rows 128-199 (72 rows) = 4608 f
#define SM_B   12800                    // B [64][768B] bf16 hi/lo = 12288 f
#define SM_W2F 25088                    // W2 b-frags hi/lo = 2048 f
#define SM_QS  27136                    // 192
#define SM_B1  (SM_QS + 192)            // 64
#define SM_W3  (SM_B1 + 64)             // 32
#define SM_B2  (SM_W3 + 32)             // 32
#define SM_SC  (SM_B2 + 32)             // 256
#define SM_WGT (SM_SC + 256)            // 256
#define SM_RED (SM_WGT + 256)           // 64
#define SMEM_FLOATS (SM_RED + 64)       // 28032 f = 112128 B -> 2 CTAs/SM

static __device__ __forceinline__ uint32_t pkbf2(float x, float y) {
    __nv_bfloat162 h = __floats2bfloat162_rn(x, y);
    return *reinterpret_cast<uint32_t*>(&h);
}

#define LDSM4(r0, r1, r2, r3, addr) \
    asm volatile("ldmatrix.sync.aligned.m8n8.x4.shared.b16 {%0,%1,%2,%3}, [%4];" \
                 : "=r"(r0), "=r"(r1), "=r"(r2), "=r"(r3) : "r"(addr))

#define MMA16816(d0, d1, d2, d3, a0, a1, a2, a3, b0, b1) \
    asm volatile("mma.sync.aligned.m16n8k16.row.col.f32.bf16.bf16.f32 " \
                 "{%0,%1,%2,%3},{%4,%5,%6,%7},{%8,%9},{%0,%1,%2,%3};" \
                 : "+f"(d0), "+f"(d1), "+f"(d2), "+f"(d3) \
                 : "r"(a0), "r"(a1), "r"(a2), "r"(a3), "r"(b0), "r"(b1))

// Convert all 200 key rows' 64-col slice [k0,k0+64) to bf16 hi/lo into A0/A1.
static __device__ __forceinline__ void conv_chunk_all(char* a0, char* a1,
                                                      const float* kbase, int k0, int tid) {
    #pragma unroll
    for (int it = 0; it < 13; it++) {
        int f = tid + it * NT;
        if (f < 3200) {
            int r = f >> 4;
            int q = f & 15;
            float4 kv = *reinterpret_cast<const float4*>(kbase + (size_t)r * DD + k0 + 4 * q);
            __nv_bfloat162 h01 = __floats2bfloat162_rn(kv.x, kv.y);
            __nv_bfloat162 h23 = __floats2bfloat162_rn(kv.z, kv.w);
            __nv_bfloat162 l01 = __floats2bfloat162_rn(kv.x - __bfloat162float(h01.x),
                                                       kv.y - __bfloat162float(h01.y));
            __nv_bfloat162 l23 = __floats2bfloat162_rn(kv.z - __bfloat162float(h23.x),
                                                       kv.w - __bfloat162float(h23.y));
            uint32_t x  = (uint32_t)(r & 7) << 4;
            char* base = (r < 128) ? (a0 + (uint32_t)r * 256u) : (a1 + (uint32_t)(r - 128) * 256u);
            uint2 hv, lv;
            hv.x = *reinterpret_cast<const uint32_t*>(&h01);
            hv.y = *reinterpret_cast<const uint32_t*>(&h23);
            lv.x = *reinterpret_cast<const uint32_t*>(&l01);
            lv.y = *reinterpret_cast<const uint32_t*>(&l23);
            *reinterpret_cast<uint2*>(base + (((uint32_t)(8 * q)) ^ x))       = hv;
            *reinterpret_cast<uint2*>(base + (((uint32_t)(128 + 8 * q)) ^ x)) = lv;
        }
    }
}

// Fused epilogue: cc (H frags, post-GEMM1) -> bias1+prelu -> MMA2 vs W2 -> bias2+prelu
// -> W3 dot -> quad-reduce -> masked scores for rows of m-group g.
static __device__ __forceinline__ void epilogue(float* cc, int g, int wid, int lid,
                                                const float* bias1, const float* b2s,
                                                const float* w3s,
                                                const uint32_t* w2fh, const uint32_t* w2fl,
                                                float a1, float a2, float b3,
                                                const int* kmask, int b, float* score) {
    #pragma unroll
    for (int j = 0; j < 8; j++) {
        float2 bb = *reinterpret_cast<const float2*>(bias1 + 8 * j + (lid & 3) * 2);
        float v0 = cc[4*j+0] + bb.x;
        float v1 = cc[4*j+1] + bb.y;
        float v2 = cc[4*j+2] + bb.x;
        float v3 = cc[4*j+3] + bb.y;
        cc[4*j+0] = (v0 >= 0.f) ? v0 : a1 * v0;
        cc[4*j+1] = (v1 >= 0.f) ? v1 : a1 * v1;
        cc[4*j+2] = (v2 >= 0.f) ? v2 : a1 * v2;
        cc[4*j+3] = (v3 >= 0.f) ? v3 : a1 * v3;
    }
    uint32_t a2h[16], a2l[16];
    #pragma unroll
    for (int kb = 0; kb < 4; kb++) {
        #pragma unroll
        for (int pos = 0; pos < 4; pos++) {
            int j = 2 * kb + (pos >> 1);
            int r0 = 4 * j + (pos & 1) * 2;
            float v0 = cc[r0], v1 = cc[r0 + 1];
            float h0 = __bfloat162float(__float2bfloat16_rn(v0));
            float h1 = __bfloat162float(__float2bfloat16_rn(v1));
            a2h[kb * 4 + pos] = pkbf2(v0, v1);
            a2l[kb * 4 + pos] = pkbf2(v0 - h0, v1 - h1);
        }
    }
    float d[16];
    #pragma unroll
    for (int j = 0; j < 16; j++) d[j] = 0.f;
    #pragma unroll
    for (int kb = 0; kb < 4; kb++) {
        uint32_t* ah = a2h + kb * 4;
        uint32_t* al = a2l + kb * 4;
        uint2 wh[4], wl[4];
        #pragma unroll
        for (int cn = 0; cn < 4; cn++) {
            wh[cn] = *reinterpret_cast<const uint2*>(w2fh + (kb * 4 + cn) * 64 + lid * 2);
            wl[cn] = *reinterpret_cast<const uint2*>(w2fl + (kb * 4 + cn) * 64 + lid * 2);
        }
        // term-major order: dependent MMAs on d[4cn] spaced 4 apart
        #pragma unroll
        for (int cn = 0; cn < 4; cn++)
            MMA16816(d[4*cn+0], d[4*cn+1], d[4*cn+2], d[4*cn+3], ah[0], ah[1], ah[2], ah[3], wh[cn].x, wh[cn].y);
        #pragma unroll
        for (int cn = 0; cn < 4; cn++)
            MMA16816(d[4*cn+0], d[4*cn+1], d[4*cn+2], d[4*cn+3], al[0], al[1], al[2], al[3], wh[cn].x, wh[cn].y);
        #pragma unroll
        for (int cn = 0; cn < 4; cn++)
            MMA16816(d[4*cn+0], d[4*cn+1], d[4*cn+2], d[4*cn+3], ah[0], ah[1], ah[2], ah[3], wl[cn].x, wl[cn].y);
    }
    float p0 = 0.f, p1 = 0.f;
    #pragma unroll
    for (int cn = 0; cn < 4; cn++) {
        int col = 8 * cn + (lid & 3) * 2;
        float2 bb = *reinterpret_cast<const float2*>(b2s + col);
        float2 ww = *reinterpret_cast<const float2*>(w3s + col);
        float v0 = d[4*cn+0] + bb.x;
        float v1 = d[4*cn+1] + bb.y;
        float v2 = d[4*cn+2] + bb.x;
        float v3 = d[4*cn+3] + bb.y;
        v0 = (v0 >= 0.f) ? v0 : a2 * v0;
        v1 = (v1 >= 0.f) ? v1 : a2 * v1;
        v2 = (v2 >= 0.f) ? v2 : a2 * v2;
        v3 = (v3 >= 0.f) ? v3 : a2 * v3;
        p0 = fmaf(v0, ww.x, p0); p0 = fmaf(v1, ww.y, p0);
        p1 = fmaf(v2, ww.x, p1); p1 = fmaf(v3, ww.y, p1);
    }
    p0 += __shfl_xor_sync(0xffffffffu, p0, 1);
    p0 += __shfl_xor_sync(0xffffffffu, p0, 2);
    p1 += __shfl_xor_sync(0xffffffffu, p1, 1);
    p1 += __shfl_xor_sync(0xffffffffu, p1, 2);
    if ((lid & 3) == 0) {
        int row0 = g * 128 + wid * 16 + (lid >> 2);
        int row1 = row0 + 8;
        if (row0 < SS) {
            int mv = kmask[(size_t)b * SS + row0];
            score[row0] = mv ? (p0 + b3) : -INFINITY;
        }
        if (row1 < SS) {
            int mv = kmask[(size_t)b * SS + row1];
            score[row1] = mv ? (p1 + b3) : -INFINITY;
        }
    }
}

__global__ __launch_bounds__(NT, 2)
void rich_attn_kernel(const float* __restrict__ query,
                      const float* __restrict__ keys,
                      const int*   __restrict__ kmask,
                      const float* __restrict__ W1,
                      const float* __restrict__ b1,
                      const float* __restrict__ a1p,
                      const float* __restrict__ W2,
                      const float* __restrict__ b2,
                      const float* __restrict__ a2p,
                      const float* __restrict__ W3,
                      const float* __restrict__ b3p,
                      float* __restrict__ out)
{
    extern __shared__ float sm[];
    const int tid = threadIdx.x;
    const int wid = tid >> 5;
    const int lid = tid & 31;
    const int b   = blockIdx.x;

    const float a1 = a1p[0];
    const float a2 = a2p[0];
    const float b3 = b3p[0];

    const float* kbase = keys + (size_t)b * SS * DD;
    char* smA0 = reinterpret_cast<char*>(sm + SM_A0);
    char* smA1 = reinterpret_cast<char*>(sm + SM_A1);
    char* smB  = reinterpret_cast<char*>(sm + SM_B);
    uint32_t* w2fh = reinterpret_cast<uint32_t*>(sm + SM_W2F);
    uint32_t* w2fl = w2fh + 1024;
    const uint32_t base_u32 = (uint32_t)__cvta_generic_to_shared((void*)sm);
    const uint32_t a0_u32 = base_u32 + SM_A0 * 4;
    const uint32_t a1_u32 = base_u32 + SM_A1 * 4;
    const uint32_t bbase_u32 = base_u32 + SM_B * 4;

    float* qs    = sm + SM_QS;
    float* bias1 = sm + SM_B1;
    float* w3s   = sm + SM_W3;
    float* b2s   = sm + SM_B2;
    float* score = sm + SM_SC;
    float* wgt   = sm + SM_WGT;
    float* red   = sm + SM_RED;

    // ---- small loads ----
    if (tid < DD) qs[tid] = query[(size_t)b * DD + tid];
    if (tid < H2) { w3s[tid] = W3[tid]; b2s[tid] = b2[tid]; }
    score[tid] = -INFINITY;
    __syncthreads();   // qs ready

    // ---- B = weffT hi/lo, swizzled [h row][hi 0..383 | lo 384..767] ----
    for (int idx = tid; idx < DD * H1; idx += NT) {
        int k = idx >> 6;
        int h = idx & 63;
        float v = W1[idx] + W1[(size_t)(576 + k) * H1 + h] + qs[k] * W1[(size_t)(384 + k) * H1 + h];
        __nv_bfloat16 hb = __float2bfloat16_rn(v);
        __nv_bfloat16 lb = __float2bfloat16_rn(v - __bfloat162float(hb));
        uint32_t x  = (uint32_t)(h & 7) << 4;
        uint32_t rb = (uint32_t)h * 768u;
        *reinterpret_cast<__nv_bfloat16*>(smB + rb + (((uint32_t)(2 * k)) ^ x))       = hb;
        *reinterpret_cast<__nv_bfloat16*>(smB + rb + (((uint32_t)(384 + 2 * k)) ^ x)) = lb;
    }
    // ---- W2 b-frags (verified layout) ----
    for (int e = tid; e < 512; e += NT) {
        int kb = e >> 7;
        int rem = e & 127;
        int cn = rem >> 5;
        int ln = rem & 31;
        int k0 = kb * 16 + (ln & 3) * 2;
        int col = cn * 8 + (ln >> 2);
        float v00 = W2[(size_t)k0 * H2 + col];
        float v01 = W2[(size_t)(k0 + 1) * H2 + col];
        float v10 = W2[(size_t)(k0 + 8) * H2 + col];
        float v11 = W2[(size_t)(k0 + 9) * H2 + col];
        float h00 = __bfloat162float(__float2bfloat16_rn(v00));
        float h01 = __bfloat162float(__float2bfloat16_rn(v01));
        float h10 = __bfloat162float(__float2bfloat16_rn(v10));
        float h11 = __bfloat162float(__float2bfloat16_rn(v11));
        int basei = (kb * 4 + cn) * 64 + ln * 2;
        w2fh[basei + 0] = pkbf2(v00, v01);
        w2fh[basei + 1] = pkbf2(v10, v11);
        w2fl[basei + 0] = pkbf2(v00 - h00, v01 - h01);
        w2fl[basei + 1] = pkbf2(v10 - h10, v11 - h11);
    }
    // ---- bias1 partials (wgt scratch) ----
    {
        int h = tid & 63;
        int c = tid >> 6;
        float acc_ = 0.f;
        int i0 = c * 48;
        #pragma unroll 8
        for (int i = i0; i < i0 + 48; i++)
            acc_ = fmaf(qs[i], W1[(size_t)(192 + i) * H1 + h] - W1[(size_t)(576 + i) * H1 + h], acc_);
        wgt[tid] = acc_;
    }
    // ---- conv chunk 0 (all rows, k 0..63) ----
    conv_chunk_all(smA0, smA1, kbase, 0, tid);
    __syncthreads();
    if (tid < H1)
        bias1[tid] = b1[tid] + wgt[tid] + wgt[tid + 64] + wgt[tid + 128] + wgt[tid + 192];
    __syncthreads();

    // ================= main: 3 k-chunks, both m-groups share B frags =================
    const uint32_t uA = ((uint32_t)(lid >> 4)) * 16u;
    const uint32_t jB = (uint32_t)(lid >> 3);
    const uint32_t uB = (jB & 1u) * 16u;
    const uint32_t xb = ((uint32_t)(lid & 7)) << 4;

    const uint32_t rowA = (uint32_t)(wid * 16 + (lid & 15));
    const uint32_t xa = (rowA & 7u) << 4;
    const uint32_t aB0 = a0_u32 + rowA * 256u;
    const uint32_t aB1 = a1_u32 + rowA * 256u;   // rows >=72 overflow into B region: garbage, masked
    const uint32_t rowB = (jB >> 1) * 8u + (uint32_t)(lid & 7);
    const uint32_t bR0 = bbase_u32 + rowB * 768u;
    const uint32_t bR1 = bR0 + 16u * 768u;
    const uint32_t bR2 = bR0 + 32u * 768u;
    const uint32_t bR3 = bR0 + 48u * 768u;

    float cc0[32], cc1[32];
    #pragma unroll
    for (int j = 0; j < 32; j++) { cc0[j] = 0.f; cc1[j] = 0.f; }

    for (int c = 0; c < 3; c++) {
        #pragma unroll
        for (int ks = 0; ks < 4; ks++) {
            uint32_t ka_h = (uint32_t)(ks * 32);
            uint32_t ka_l = ka_h + 128u;
            uint32_t kb_h = (uint32_t)(c * 128 + ks * 32);
            uint32_t kb_l = kb_h + 384u;

            // B frags once (8 LDSM4)
            uint32_t bh[16], bl[16];
            LDSM4(bh[0],  bh[1],  bh[2],  bh[3],  bR0 + ((kb_h + uB) ^ xb));
            LDSM4(bh[4],  bh[5],  bh[6],  bh[7],  bR1 + ((kb_h + uB) ^ xb));
            LDSM4(bh[8],  bh[9],  bh[10], bh[11], bR2 + ((kb_h + uB) ^ xb));
            LDSM4(bh[12], bh[13], bh[14], bh[15], bR3 + ((kb_h + uB) ^ xb));
            LDSM4(bl[0],  bl[1],  bl[2],  bl[3],  bR0 + ((kb_l + uB) ^ xb));
            LDSM4(bl[4],  bl[5],  bl[6],  bl[7],  bR1 + ((kb_l + uB) ^ xb));
            LDSM4(bl[8],  bl[9],  bl[10], bl[11], bR2 + ((kb_l + uB) ^ xb));
            LDSM4(bl[12], bl[13], bl[14], bl[15], bR3 + ((kb_l + uB) ^ xb));

            // ---- g0 ----
            {
                uint32_t ah0, ah1, ah2, ah3, al0, al1, al2, al3;
                LDSM4(ah0, ah1, ah2, ah3, aB0 + ((ka_h + uA) ^ xa));
                LDSM4(al0, al1, al2, al3, aB0 + ((ka_l + uA) ^ xa));
                #pragma unroll
                for (int gg = 0; gg < 8; gg++)
                    MMA16816(cc0[4*gg+0], cc0[4*gg+1], cc0[4*gg+2], cc0[4*gg+3],
                             ah0, ah1, ah2, ah3, bh[2*gg], bh[2*gg+1]);
                #pragma unroll
                for (int gg = 0; gg < 8; gg++)
                    MMA16816(cc0[4*gg+0], cc0[4*gg+1], cc0[4*gg+2], cc0[4*gg+3],
                             al0, al1, al2, al3, bh[2*gg], bh[2*gg+1]);
                #pragma unroll
                for (int gg = 0; gg < 8; gg++)
                    MMA16816(cc0[4*gg+0], cc0[4*gg+1], cc0[4*gg+2], cc0[4*gg+3],
                             ah0, ah1, ah2, ah3, bl[2*gg], bl[2*gg+1]);
            }
            // ---- g1 ----
            {
                uint32_t ah0, ah1, ah2, ah3, al0, al1, al2, al3;
                LDSM4(ah0, ah1, ah2, ah3, aB1 + ((ka_h + uA) ^ xa));
                LDSM4(al0, al1, al2, al3, aB1 + ((ka_l + uA) ^ xa));
                #pragma unroll
                for (int gg = 0; gg < 8; gg++)
                    MMA16816(cc1[4*gg+0], cc1[4*gg+1], cc1[4*gg+2], cc1[4*gg+3],
                             ah0, ah1, ah2, ah3, bh[2*gg], bh[2*gg+1]);
                #pragma unroll
                for (int gg = 0; gg < 8; gg++)
                    MMA16816(cc1[4*gg+0], cc1[4*gg+1], cc1[4*gg+2], cc1[4*gg+3],
                             al0, al1, al2, al3, bh[2*gg], bh[2*gg+1]);
                #pragma unroll
                for (int gg = 0; gg < 8; gg++)
                    MMA16816(cc1[4*gg+0], cc1[4*gg+1], cc1[4*gg+2], cc1[4*gg+3],
                             ah0, ah1, ah2, ah3, bl[2*gg], bl[2*gg+1]);
            }
        }
        __syncthreads();          // all reads of chunk c done
        if (c < 2) {
            conv_chunk_all(smA0, smA1, kbase, (c + 1) * 64, tid);
            __syncthreads();      // next chunk ready
        }
    }

    // ---- fused epilogues (no A/B use) ----
    epilogue(cc0, 0, wid, lid, bias1, b2s, w3s, w2fh, w2fl, a1, a2, b3, kmask, b, score);
    epilogue(cc1, 1, wid, lid, bias1, b2s, w3s, w2fh, w2fl, a1, a2, b3, kmask, b, score);
    __syncthreads();

    // ---- softmax via warp shuffles ----
    const float myscore = score[tid];
    float v = myscore;
    #pragma unroll
    for (int off = 16; off > 0; off >>= 1)
        v = fmaxf(v, __shfl_xor_sync(0xffffffffu, v, off));
    if (lid == 0) red[wid] = v;
    __syncthreads();
    if (tid < 32) {
        float mv = (tid < 8) ? red[tid] : -INFINITY;
        #pragma unroll
        for (int off = 4; off > 0; off >>= 1)
            mv = fmaxf(mv, __shfl_xor_sync(0xffffffffu, mv, off));
        if (tid == 0) red[32] = mv;
    }
    __syncthreads();
    const float m = red[32];

    float e = 0.f;
    if (tid < SS && m > -INFINITY && myscore > -INFINITY)
        e = expf(myscore - m);
    float es = e;
    #pragma unroll
    for (int off = 16; off > 0; off >>= 1)
        es += __shfl_xor_sync(0xffffffffu, es, off);
    if (lid == 0) red[wid] = es;
    __syncthreads();
    if (tid < 32) {
        float sv = (tid < 8) ? red[tid] : 0.f;
        #pragma unroll
        for (int off = 4; off > 0; off >>= 1)
            sv += __shfl_xor_sync(0xffffffffu, sv, off);
        if (tid == 0) red[32] = (sv > 0.f) ? (1.f / sv) : 0.f;
    }
    __syncthreads();
    const float inv = red[32];

    {
        float wv = e * inv;
        wgt[tid] = wv;
        if (tid < SS) out[(size_t)BB * DD + (size_t)b * SS + tid] = wv;
    }
    __syncthreads();

    // ---- weighted sum: out[b,d] = sum_s wgt[s]*keys[b,s,d], 4 ILP streams ----
    if (tid < DD) {
        const float* kb = kbase + tid;
        float acc0 = 0.f, acc1 = 0.f, acc2_ = 0.f, acc3 = 0.f;
        #pragma unroll 5
        for (int si = 0; si < 50; si++) {
            acc0  = fmaf(wgt[si],       kb[(size_t)si * DD],          acc0);
            acc1  = fmaf(wgt[si + 50],  kb[(size_t)(si + 50) * DD],   acc1);
            acc2_ = fmaf(wgt[si + 100], kb[(size_t)(si + 100) * DD],  acc2_);
            acc3  = fmaf(wgt[si + 150], kb[(size_t)(si + 150) * DD],  acc3);
        }
        out[(size_t)b * DD + tid] = (acc0 + acc1) + (acc2_ + acc3);
    }
}

extern "C" void kernel_launch(void* const* d_in, const int* in_sizes, int n_in,
                              void* d_out, int out_size)
{
    const float* query = (const float*)d_in[0];
    const float* keys  = (const float*)d_in[1];
    const int*   mask  = (const int*)  d_in[2];
    const float* W1    = (const float*)d_in[3];
    const float* b1    = (const float*)d_in[4];
    const float* a1    = (const float*)d_in[5];
    const float* W2    = (const float*)d_in[6];
    const float* b2    = (const float*)d_in[7];
    const float* a2    = (const float*)d_in[8];
    const float* W3    = (const float*)d_in[9];
    const float* b3    = (const float*)d_in[10];
    float* out = (float*)d_out;

    static bool attr_set = false;
    if (!attr_set) {
        cudaFuncSetAttribute(rich_attn_kernel,
                             cudaFuncAttributeMaxDynamicSharedMemorySize,
                             SMEM_FLOATS * sizeof(float));
        attr_set = true;
    }

    rich_attn_kernel<<<BB, NT, SMEM_FLOATS * sizeof(float)>>>(
        query, keys, mask, W1, b1, a1, W2, b2, a2, W3, b3, out);
}

// round 16
// speedup vs baseline: 1.0662x; 1.0662x over previous
#include <cuda_runtime.h>
#include <cuda_bf16.h>
#include <math.h>
#include <stdint.h>

#define BB 2048
#define SS 200
#define DD 192
#define H1 64
#define H2 32
#define NT 256

typedef unsigned long long ull;

// ---- smem layout (float idx) ----
#define SM_AB  0                        // A chunk: 128 rows * 256B = 32768 B = 8192 f
#define SM_B   8192                     // B [64][768B] bf16 hi/lo = 49152 B = 12288 f
#define SM_W2F 20480                    // W2 b-frags hi(1024 u32) + lo(1024 u32) = 2048 f
#define SM_QS  22528                    // 192
#define SM_B1  (SM_QS + 192)            // 64
#define SM_W3  (SM_B1 + 64)             // 32
#define SM_B2  (SM_W3 + 32)             // 32
#define SM_SC  (SM_B2 + 32)             // 256
#define SM_WGT (SM_SC + 256)            // 256
#define SM_RED (SM_WGT + 256)           // 64
#define SMEM_FLOATS (SM_RED + 64)       // 23424 f = 93696 B -> 2 CTAs/SM

static __device__ __forceinline__ uint32_t pkbf2(float x, float y) {
    __nv_bfloat162 h = __floats2bfloat162_rn(x, y);
    return *reinterpret_cast<uint32_t*>(&h);
}

#define LDSM4(r0, r1, r2, r3, addr) \
    asm volatile("ldmatrix.sync.aligned.m8n8.x4.shared.b16 {%0,%1,%2,%3}, [%4];" \
                 : "=r"(r0), "=r"(r1), "=r"(r2), "=r"(r3) : "r"(addr))

#define MMA16816(d0, d1, d2, d3, a0, a1, a2, a3, b0, b1) \
    asm volatile("mma.sync.aligned.m16n8k16.row.col.f32.bf16.bf16.f32 " \
                 "{%0,%1,%2,%3},{%4,%5,%6,%7},{%8,%9},{%0,%1,%2,%3};" \
                 : "+f"(d0), "+f"(d1), "+f"(d2), "+f"(d3) \
                 : "r"(a0), "r"(a1), "r"(a2), "r"(a3), "r"(b0), "r"(b1))

// LDG phase: fetch 8 float4 of chunk (row0, k0) into regs.
static __device__ __forceinline__ void conv_ldg(float4* pf, const float* kbase,
                                                int row0, int k0, int tid) {
    #pragma unroll
    for (int it = 0; it < 8; it++) {
        int f = tid + it * NT;
        int r = f >> 4;
        int q = f & 15;
        int grow = row0 + r;
        pf[it] = make_float4(0.f, 0.f, 0.f, 0.f);
        if (grow < SS)
            pf[it] = *reinterpret_cast<const float4*>(kbase + (size_t)grow * DD + k0 + 4 * q);
    }
}

// STS phase: convert prefetched regs to bf16 hi/lo and store swizzled.
static __device__ __forceinline__ void conv_sts(char* abuf, const float4* pf, int tid) {
    #pragma unroll
    for (int it = 0; it < 8; it++) {
        int f = tid + it * NT;
        int r = f >> 4;
        int q = f & 15;
        float4 kv = pf[it];
        __nv_bfloat162 h01 = __floats2bfloat162_rn(kv.x, kv.y);
        __nv_bfloat162 h23 = __floats2bfloat162_rn(kv.z, kv.w);
        __nv_bfloat162 l01 = __floats2bfloat162_rn(kv.x - __bfloat162float(h01.x),
                                                   kv.y - __bfloat162float(h01.y));
        __nv_bfloat162 l23 = __floats2bfloat162_rn(kv.z - __bfloat162float(h23.x),
                                                   kv.w - __bfloat162float(h23.y));
        uint32_t x  = (uint32_t)(r & 7) << 4;
        uint32_t rb = (uint32_t)r * 256u;
        uint2 hv, lv;
        hv.x = *reinterpret_cast<const uint32_t*>(&h01);
        hv.y = *reinterpret_cast<const uint32_t*>(&h23);
        lv.x = *reinterpret_cast<const uint32_t*>(&l01);
        lv.y = *reinterpret_cast<const uint32_t*>(&l23);
        *reinterpret_cast<uint2*>(abuf + rb + (((uint32_t)(8 * q)) ^ x))       = hv;
        *reinterpret_cast<uint2*>(abuf + rb + (((uint32_t)(128 + 8 * q)) ^ x)) = lv;
    }
}

__global__ __launch_bounds__(NT, 2)
void rich_attn_kernel(const float* __restrict__ query,
                      const float* __restrict__ keys,
                      const int*   __restrict__ kmask,
                      const float* __restrict__ W1,
                      const float* __restrict__ b1,
                      const float* __restrict__ a1p,
                      const float* __restrict__ W2,
                      const float* __restrict__ b2,
                      const float* __restrict__ a2p,
                      const float* __restrict__ W3,
                      const float* __restrict__ b3p,
                      float* __restrict__ out)
{
    extern __shared__ float sm[];
    const int tid = threadIdx.x;
    const int wid = tid >> 5;
    const int lid = tid & 31;
    const int b   = blockIdx.x;

    const float a1 = a1p[0];
    const float a2 = a2p[0];
    const float b3 = b3p[0];

    const float* kbase = keys + (size_t)b * SS * DD;
    char* abuf = reinterpret_cast<char*>(sm + SM_AB);
    char* smB  = reinterpret_cast<char*>(sm + SM_B);
    uint32_t* w2fh = reinterpret_cast<uint32_t*>(sm + SM_W2F);
    uint32_t* w2fl = w2fh + 1024;
    const uint32_t base_u32 = (uint32_t)__cvta_generic_to_shared((void*)sm);
    const uint32_t abase_u32 = base_u32;
    const uint32_t bbase_u32 = base_u32 + SM_B * 4;

    float* qs    = sm + SM_QS;
    float* bias1 = sm + SM_B1;
    float* w3s   = sm + SM_W3;
    float* b2s   = sm + SM_B2;
    float* score = sm + SM_SC;
    float* wgt   = sm + SM_WGT;
    float* red   = sm + SM_RED;

    // ---- prefetch conv chunk (0,0) under the whole prologue ----
    float4 pf[8];
    conv_ldg(pf, kbase, 0, 0, tid);

    // ---- small loads ----
    if (tid < DD) qs[tid] = query[(size_t)b * DD + tid];
    if (tid < H2) { w3s[tid] = W3[tid]; b2s[tid] = b2[tid]; }
    score[tid] = -INFINITY;
    __syncthreads();   // qs ready

    // ---- B = weffT hi/lo, swizzled [h row][hi 0..383 | lo 384..767] ----
    for (int idx = tid; idx < DD * H1; idx += NT) {
        int k = idx >> 6;
        int h = idx & 63;
        float v = W1[idx] + W1[(size_t)(576 + k) * H1 + h] + qs[k] * W1[(size_t)(384 + k) * H1 + h];
        __nv_bfloat16 hb = __float2bfloat16_rn(v);
        __nv_bfloat16 lb = __float2bfloat16_rn(v - __bfloat162float(hb));
        uint32_t x  = (uint32_t)(h & 7) << 4;
        uint32_t rb = (uint32_t)h * 768u;
        *reinterpret_cast<__nv_bfloat16*>(smB + rb + (((uint32_t)(2 * k)) ^ x))       = hb;
        *reinterpret_cast<__nv_bfloat16*>(smB + rb + (((uint32_t)(384 + 2 * k)) ^ x)) = lb;
    }
    // ---- W2 b-frags (col-major k16n8, hi/lo) — verified layout ----
    for (int e = tid; e < 512; e += NT) {
        int kb = e >> 7;
        int rem = e & 127;
        int cn = rem >> 5;
        int ln = rem & 31;
        int k0 = kb * 16 + (ln & 3) * 2;
        int col = cn * 8 + (ln >> 2);
        float v00 = W2[(size_t)k0 * H2 + col];
        float v01 = W2[(size_t)(k0 + 1) * H2 + col];
        float v10 = W2[(size_t)(k0 + 8) * H2 + col];
        float v11 = W2[(size_t)(k0 + 9) * H2 + col];
        float h00 = __bfloat162float(__float2bfloat16_rn(v00));
        float h01 = __bfloat162float(__float2bfloat16_rn(v01));
        float h10 = __bfloat162float(__float2bfloat16_rn(v10));
        float h11 = __bfloat162float(__float2bfloat16_rn(v11));
        int basei = (kb * 4 + cn) * 64 + ln * 2;
        w2fh[basei + 0] = pkbf2(v00, v01);
        w2fh[basei + 1] = pkbf2(v10, v11);
        w2fl[basei + 0] = pkbf2(v00 - h00, v01 - h01);
        w2fl[basei + 1] = pkbf2(v10 - h10, v11 - h11);
    }
    // ---- bias1 partials (wgt scratch), high ILP ----
    {
        int h = tid & 63;
        int c = tid >> 6;
        float acc_ = 0.f;
        int i0 = c * 48;
        #pragma unroll 8
        for (int i = i0; i < i0 + 48; i++)
            acc_ = fmaf(qs[i], W1[(size_t)(192 + i) * H1 + h] - W1[(size_t)(576 + i) * H1 + h], acc_);
        wgt[tid] = acc_;
    }
    // ---- store conv chunk (0,0) ----
    conv_sts(abuf, pf, tid);
    __syncthreads();
    if (tid < H1)
        bias1[tid] = b1[tid] + wgt[tid] + wgt[tid + 64] + wgt[tid + 128] + wgt[tid + 192];
    __syncthreads();

    // ================= main: 2 m-groups x 3 k-chunks, 8 warps n64 =================
    const uint32_t uA = ((uint32_t)(lid >> 4)) * 16u;
    const uint32_t jB = (uint32_t)(lid >> 3);
    const uint32_t uB = (jB & 1u) * 16u;
    const uint32_t xb = ((uint32_t)(lid & 7)) << 4;

    const uint32_t rowA = (uint32_t)(wid * 16 + (lid & 15));
    const uint32_t xa = (rowA & 7u) << 4;
    const uint32_t aB = abase_u32 + rowA * 256u;
    const uint32_t rowB = (jB >> 1) * 8u + (uint32_t)(lid & 7);
    const uint32_t bB0 = bbase_u32 + rowB * 768u;
    const uint32_t bB1 = bB0 + 16u * 768u;
    const uint32_t bB2 = bB0 + 32u * 768u;
    const uint32_t bB3 = bB0 + 48u * 768u;

    for (int g = 0; g < 2; g++) {
        float cc[32];
        #pragma unroll
        for (int j = 0; j < 32; j++) cc[j] = 0.f;

        for (int c = 0; c < 3; c++) {
            const bool has_next = !(g == 1 && c == 2);
            // prefetch next chunk's keys into regs (hidden under GEMM below)
            if (has_next) {
                int ng = (c == 2) ? g + 1 : g;
                int nc = (c == 2) ? 0 : c + 1;
                conv_ldg(pf, kbase, ng * 128, nc * 64, tid);
            }

            // GEMM1 on chunk (g, c): 4 k16 steps, term-major MMA scheduling
            #pragma unroll
            for (int ks = 0; ks < 4; ks++) {
                uint32_t ka_h = (uint32_t)(ks * 32);
                uint32_t ka_l = ka_h + 128u;
                uint32_t kb_h = (uint32_t)(c * 128 + ks * 32);
                uint32_t kb_l = kb_h + 384u;
                uint32_t ah0, ah1, ah2, ah3, al0, al1, al2, al3;
                LDSM4(ah0, ah1, ah2, ah3, aB + ((ka_h + uA) ^ xa));
                LDSM4(al0, al1, al2, al3, aB + ((ka_l + uA) ^ xa));
                uint32_t bh[8], bl[8];
                LDSM4(bh[0], bh[1], bh[2], bh[3], bB0 + ((kb_h + uB) ^ xb));
                LDSM4(bh[4], bh[5], bh[6], bh[7], bB1 + ((kb_h + uB) ^ xb));
                LDSM4(bl[0], bl[1], bl[2], bl[3], bB0 + ((kb_l + uB) ^ xb));
                LDSM4(bl[4], bl[5], bl[6], bl[7], bB1 + ((kb_l + uB) ^ xb));
                #pragma unroll
                for (int gg = 0; gg < 4; gg++)
                    MMA16816(cc[4*gg+0], cc[4*gg+1], cc[4*gg+2], cc[4*gg+3],
                             ah0, ah1, ah2, ah3, bh[2*gg], bh[2*gg+1]);
                #pragma unroll
                for (int gg = 0; gg < 4; gg++)
                    MMA16816(cc[4*gg+0], cc[4*gg+1], cc[4*gg+2], cc[4*gg+3],
                             al0, al1, al2, al3, bh[2*gg], bh[2*gg+1]);
                #pragma unroll
                for (int gg = 0; gg < 4; gg++)
                    MMA16816(cc[4*gg+0], cc[4*gg+1], cc[4*gg+2], cc[4*gg+3],
                             ah0, ah1, ah2, ah3, bl[2*gg], bl[2*gg+1]);
                LDSM4(bh[0], bh[1], bh[2], bh[3], bB2 + ((kb_h + uB) ^ xb));
                LDSM4(bh[4], bh[5], bh[6], bh[7], bB3 + ((kb_h + uB) ^ xb));
                LDSM4(bl[0], bl[1], bl[2], bl[3], bB2 + ((kb_l + uB) ^ xb));
                LDSM4(bl[4], bl[5], bl[6], bl[7], bB3 + ((kb_l + uB) ^ xb));
                #pragma unroll
                for (int gg = 0; gg < 4; gg++)
                    MMA16816(cc[4*(gg+4)+0], cc[4*(gg+4)+1], cc[4*(gg+4)+2], cc[4*(gg+4)+3],
                             ah0, ah1, ah2, ah3, bh[2*gg], bh[2*gg+1]);
                #pragma unroll
                for (int gg = 0; gg < 4; gg++)
                    MMA16816(cc[4*(gg+4)+0], cc[4*(gg+4)+1], cc[4*(gg+4)+2], cc[4*(gg+4)+3],
                             al0, al1, al2, al3, bh[2*gg], bh[2*gg+1]);
                #pragma unroll
                for (int gg = 0; gg < 4; gg++)
                    MMA16816(cc[4*(gg+4)+0], cc[4*(gg+4)+1], cc[4*(gg+4)+2], cc[4*(gg+4)+3],
                             ah0, ah1, ah2, ah3, bl[2*gg], bl[2*gg+1]);
            }
            __syncthreads();       // all warps done reading A-buf chunk (g,c)

            // store next chunk (regs -> A-buf)
            if (has_next) conv_sts(abuf, pf, tid);

            // fused epilogue after the last chunk of this m-group (no A-buf use)
            if (c == 2) {
                #pragma unroll
                for (int j = 0; j < 8; j++) {
                    float2 bb = *reinterpret_cast<const float2*>(bias1 + 8 * j + (lid & 3) * 2);
                    float v0 = cc[4*j+0] + bb.x;
                    float v1 = cc[4*j+1] + bb.y;
                    float v2 = cc[4*j+2] + bb.x;
                    float v3 = cc[4*j+3] + bb.y;
                    cc[4*j+0] = (v0 >= 0.f) ? v0 : a1 * v0;
                    cc[4*j+1] = (v1 >= 0.f) ? v1 : a1 * v1;
                    cc[4*j+2] = (v2 >= 0.f) ? v2 : a1 * v2;
                    cc[4*j+3] = (v3 >= 0.f) ? v3 : a1 * v3;
                }
                uint32_t a2h[16], a2l[16];
                #pragma unroll
                for (int kb = 0; kb < 4; kb++) {
                    #pragma unroll
                    for (int pos = 0; pos < 4; pos++) {
                        int j = 2 * kb + (pos >> 1);
                        int r0 = 4 * j + (pos & 1) * 2;
                        float v0 = cc[r0], v1 = cc[r0 + 1];
                        float h0 = __bfloat162float(__float2bfloat16_rn(v0));
                        float h1 = __bfloat162float(__float2bfloat16_rn(v1));
                        a2h[kb * 4 + pos] = pkbf2(v0, v1);
                        a2l[kb * 4 + pos] = pkbf2(v0 - h0, v1 - h1);
                    }
                }
                float d[16];
                #pragma unroll
                for (int j = 0; j < 16; j++) d[j] = 0.f;
                #pragma unroll
                for (int kb = 0; kb < 4; kb++) {
                    uint32_t* ah = a2h + kb * 4;
                    uint32_t* al = a2l + kb * 4;
                    uint2 wh[4], wl[4];
                    #pragma unroll
                    for (int cn = 0; cn < 4; cn++) {
                        wh[cn] = *reinterpret_cast<const uint2*>(w2fh + (kb * 4 + cn) * 64 + lid * 2);
                        wl[cn] = *reinterpret_cast<const uint2*>(w2fl + (kb * 4 + cn) * 64 + lid * 2);
                    }
                    // term-major: dependent MMAs on d[4cn] spaced 4 apart
                    #pragma unroll
                    for (int cn = 0; cn < 4; cn++)
                        MMA16816(d[4*cn+0], d[4*cn+1], d[4*cn+2], d[4*cn+3],
                                 ah[0], ah[1], ah[2], ah[3], wh[cn].x, wh[cn].y);
                    #pragma unroll
                    for (int cn = 0; cn < 4; cn++)
                        MMA16816(d[4*cn+0], d[4*cn+1], d[4*cn+2], d[4*cn+3],
                                 al[0], al[1], al[2], al[3], wh[cn].x, wh[cn].y);
                    #pragma unroll
                    for (int cn = 0; cn < 4; cn++)
                        MMA16816(d[4*cn+0], d[4*cn+1], d[4*cn+2], d[4*cn+3],
                                 ah[0], ah[1], ah[2], ah[3], wl[cn].x, wl[cn].y);
                }
                float p0 = 0.f, p1 = 0.f;
                #pragma unroll
                for (int cn = 0; cn < 4; cn++) {
                    int col = 8 * cn + (lid & 3) * 2;
                    float2 bb = *reinterpret_cast<const float2*>(b2s + col);
                    float2 ww = *reinterpret_cast<const float2*>(w3s + col);
                    float v0 = d[4*cn+0] + bb.x;
                    float v1 = d[4*cn+1] + bb.y;
                    float v2 = d[4*cn+2] + bb.x;
                    float v3 = d[4*cn+3] + bb.y;
                    v0 = (v0 >= 0.f) ? v0 : a2 * v0;
                    v1 = (v1 >= 0.f) ? v1 : a2 * v1;
                    v2 = (v2 >= 0.f) ? v2 : a2 * v2;
                    v3 = (v3 >= 0.f) ? v3 : a2 * v3;
                    p0 = fmaf(v0, ww.x, p0); p0 = fmaf(v1, ww.y, p0);
                    p1 = fmaf(v2, ww.x, p1); p1 = fmaf(v3, ww.y, p1);
                }
                p0 += __shfl_xor_sync(0xffffffffu, p0, 1);
                p0 += __shfl_xor_sync(0xffffffffu, p0, 2);
                p1 += __shfl_xor_sync(0xffffffffu, p1, 1);
                p1 += __shfl_xor_sync(0xffffffffu, p1, 2);
                if ((lid & 3) == 0) {
                    int row0 = g * 128 + wid * 16 + (lid >> 2);
                    int row1 = row0 + 8;
                    if (row0 < SS) {
                        int mv = kmask[(size_t)b * SS + row0];
                        score[row0] = mv ? (p0 + b3) : -INFINITY;
                    }
                    if (row1 < SS) {
                        int mv = kmask[(size_t)b * SS + row1];
                        score[row1] = mv ? (p1 + b3) : -INFINITY;
                    }
                }
            }
            __syncthreads();       // next chunk in smem / scores visible
        }
    }

    // ---- softmax via warp shuffles ----
    const float myscore = score[tid];
    float v = myscore;
    #pragma unroll
    for (int off = 16; off > 0; off >>= 1)
        v = fmaxf(v, __shfl_xor_sync(0xffffffffu, v, off));
    if (lid == 0) red[wid] = v;
    __syncthreads();
    if (tid < 32) {
        float mv = (tid < 8) ? red[tid] : -INFINITY;
        #pragma unroll
        for (int off = 4; off > 0; off >>= 1)
            mv = fmaxf(mv, __shfl_xor_sync(0xffffffffu, mv, off));
        if (tid == 0) red[32] = mv;
    }
    __syncthreads();
    const float m = red[32];

    float e = 0.f;
    if (tid < SS && m > -INFINITY && myscore > -INFINITY)
        e = expf(myscore - m);
    float es = e;
    #pragma unroll
    for (int off = 16; off > 0; off >>= 1)
        es += __shfl_xor_sync(0xffffffffu, es, off);
    if (lid == 0) red[wid] = es;
    __syncthreads();
    if (tid < 32) {
        float sv = (tid < 8) ? red[tid] : 0.f;
        #pragma unroll
        for (int off = 4; off > 0; off >>= 1)
            sv += __shfl_xor_sync(0xffffffffu, sv, off);
        if (tid == 0) red[32] = (sv > 0.f) ? (1.f / sv) : 0.f;
    }
    __syncthreads();
    const float inv = red[32];

    {
        float wv = e * inv;
        wgt[tid] = wv;
        if (tid < SS) out[(size_t)BB * DD + (size_t)b * SS + tid] = wv;
    }
    __syncthreads();

    // ---- weighted sum: out[b,d] = sum_s wgt[s]*keys[b,s,d], 4 streams x unroll 10 ----
    if (tid < DD) {
        const float* kb = kbase + tid;
        float acc0 = 0.f, acc1 = 0.f, acc2_ = 0.f, acc3 = 0.f;
        #pragma unroll 10
        for (int si = 0; si < 50; si++) {
            acc0  = fmaf(wgt[si],       kb[(size_t)si * DD],          acc0);
            acc1  = fmaf(wgt[si + 50],  kb[(size_t)(si + 50) * DD],   acc1);
            acc2_ = fmaf(wgt[si + 100], kb[(size_t)(si + 100) * DD],  acc2_);
            acc3  = fmaf(wgt[si + 150], kb[(size_t)(si + 150) * DD],  acc3);
        }
        out[(size_t)b * DD + tid] = (acc0 + acc1) + (acc2_ + acc3);
    }
}

extern "C" void kernel_launch(void* const* d_in, const int* in_sizes, int n_in,
                              void* d_out, int out_size)
{
    const float* query = (const float*)d_in[0];
    const float* keys  = (const float*)d_in[1];
    const int*   mask  = (const int*)  d_in[2];
    const float* W1    = (const float*)d_in[3];
    const float* b1    = (const float*)d_in[4];
    const float* a1    = (const float*)d_in[5];
    const float* W2    = (const float*)d_in[6];
    const float* b2    = (const float*)d_in[7];
    const float* a2    = (const float*)d_in[8];
    const float* W3    = (const float*)d_in[9];
    const float* b3    = (const float*)d_in[10];
    float* out = (float*)d_out;

    static bool attr_set = false;
    if (!attr_set) {
        cudaFuncSetAttribute(rich_attn_kernel,
                             cudaFuncAttributeMaxDynamicSharedMemorySize,
                             SMEM_FLOATS * sizeof(float));
        attr_set = true;
    }

    rich_attn_kernel<<<BB, NT, SMEM_FLOATS * sizeof(float)>>>(
        query, keys, mask, W1, b1, a1, W2, b2, a2, W3, b3, out);
}

// round 17
// speedup vs baseline: 1.1303x; 1.0601x over previous
#include <cuda_runtime.h>
#include <cuda_bf16.h>
#include <math.h>
#include <stdint.h>

#define BB 2048
#define SS 200
#define DD 192
#define H1 64
#define H2 32
#define NT 256

typedef unsigned long long ull;

// ---- smem layout (float idx) ----
#define SM_AB  0                        // A chunk: 128 rows * 256B = 32768 B = 8192 f
#define SM_B   8192                     // B [64][768B] bf16 hi/lo = 49152 B = 12288 f
#define SM_W2F 20480                    // W2 b-frags hi(1024 u32) + lo(1024 u32) = 2048 f
#define SM_QS  22528                    // 192
#define SM_B1  (SM_QS + 192)            // 64
#define SM_W3  (SM_B1 + 64)             // 32
#define SM_B2  (SM_W3 + 32)             // 32
#define SM_SC  (SM_B2 + 32)             // 256
#define SM_WGT (SM_SC + 256)            // 256  (bias scratch -> kmask cache -> softmax weights)
#define SM_RED (SM_WGT + 256)           // 64
#define SMEM_FLOATS (SM_RED + 64)       // 23424 f = 93696 B -> 2 CTAs/SM

static __device__ __forceinline__ uint32_t pkbf2(float x, float y) {
    __nv_bfloat162 h = __floats2bfloat162_rn(x, y);
    return *reinterpret_cast<uint32_t*>(&h);
}

#define LDSM4(r0, r1, r2, r3, addr) \
    asm volatile("ldmatrix.sync.aligned.m8n8.x4.shared.b16 {%0,%1,%2,%3}, [%4];" \
                 : "=r"(r0), "=r"(r1), "=r"(r2), "=r"(r3) : "r"(addr))

#define MMA16816(d0, d1, d2, d3, a0, a1, a2, a3, b0, b1) \
    asm volatile("mma.sync.aligned.m16n8k16.row.col.f32.bf16.bf16.f32 " \
                 "{%0,%1,%2,%3},{%4,%5,%6,%7},{%8,%9},{%0,%1,%2,%3};" \
                 : "+f"(d0), "+f"(d1), "+f"(d2), "+f"(d3) \
                 : "r"(a0), "r"(a1), "r"(a2), "r"(a3), "r"(b0), "r"(b1))

// LDG phase: fetch 8 float4 of chunk (row0, k0) into regs.
static __device__ __forceinline__ void conv_ldg(float4* pf, const float* kbase,
                                                int row0, int k0, int tid) {
    #pragma unroll
    for (int it = 0; it < 8; it++) {
        int f = tid + it * NT;
        int r = f >> 4;
        int q = f & 15;
        int grow = row0 + r;
        pf[it] = make_float4(0.f, 0.f, 0.f, 0.f);
        if (grow < SS)
            pf[it] = *reinterpret_cast<const float4*>(kbase + (size_t)grow * DD + k0 + 4 * q);
    }
}

// STS phase: convert prefetched regs to bf16 hi/lo and store swizzled.
static __device__ __forceinline__ void conv_sts(char* abuf, const float4* pf, int tid) {
    #pragma unroll
    for (int it = 0; it < 8; it++) {
        int f = tid + it * NT;
        int r = f >> 4;
        int q = f & 15;
        float4 kv = pf[it];
        __nv_bfloat162 h01 = __floats2bfloat162_rn(kv.x, kv.y);
        __nv_bfloat162 h23 = __floats2bfloat162_rn(kv.z, kv.w);
        __nv_bfloat162 l01 = __floats2bfloat162_rn(kv.x - __bfloat162float(h01.x),
                                                   kv.y - __bfloat162float(h01.y));
        __nv_bfloat162 l23 = __floats2bfloat162_rn(kv.z - __bfloat162float(h23.x),
                                                   kv.w - __bfloat162float(h23.y));
        uint32_t x  = (uint32_t)(r & 7) << 4;
        uint32_t rb = (uint32_t)r * 256u;
        uint2 hv, lv;
        hv.x = *reinterpret_cast<const uint32_t*>(&h01);
        hv.y = *reinterpret_cast<const uint32_t*>(&h23);
        lv.x = *reinterpret_cast<const uint32_t*>(&l01);
        lv.y = *reinterpret_cast<const uint32_t*>(&l23);
        *reinterpret_cast<uint2*>(abuf + rb + (((uint32_t)(8 * q)) ^ x))       = hv;
        *reinterpret_cast<uint2*>(abuf + rb + (((uint32_t)(128 + 8 * q)) ^ x)) = lv;
    }
}

__global__ __launch_bounds__(NT, 2)
void rich_attn_kernel(const float* __restrict__ query,
                      const float* __restrict__ keys,
                      const int*   __restrict__ kmask,
                      const float* __restrict__ W1,
                      const float* __restrict__ b1,
                      const float* __restrict__ a1p,
                      const float* __restrict__ W2,
                      const float* __restrict__ b2,
                      const float* __restrict__ a2p,
                      const float* __restrict__ W3,
                      const float* __restrict__ b3p,
                      float* __restrict__ out)
{
    extern __shared__ float sm[];
    const int tid = threadIdx.x;
    const int wid = tid >> 5;
    const int lid = tid & 31;
    const int b   = blockIdx.x;

    const float a1 = a1p[0];
    const float a2 = a2p[0];
    const float b3 = b3p[0];

    const float* kbase = keys + (size_t)b * SS * DD;
    char* abuf = reinterpret_cast<char*>(sm + SM_AB);
    char* smB  = reinterpret_cast<char*>(sm + SM_B);
    uint32_t* w2fh = reinterpret_cast<uint32_t*>(sm + SM_W2F);
    uint32_t* w2fl = w2fh + 1024;
    const uint32_t base_u32 = (uint32_t)__cvta_generic_to_shared((void*)sm);
    const uint32_t abase_u32 = base_u32;
    const uint32_t bbase_u32 = base_u32 + SM_B * 4;

    float* qs    = sm + SM_QS;
    float* bias1 = sm + SM_B1;
    float* w3s   = sm + SM_W3;
    float* b2s   = sm + SM_B2;
    float* score = sm + SM_SC;
    float* wgt   = sm + SM_WGT;
    int*   kms   = reinterpret_cast<int*>(sm + SM_WGT);   // kmask cache (aliases wgt; disjoint in time)
    float* red   = sm + SM_RED;

    // ---- prefetch conv chunk (0,0) under the whole prologue ----
    float4 pf[8];
    conv_ldg(pf, kbase, 0, 0, tid);

    // ---- small loads ----
    if (tid < DD) qs[tid] = query[(size_t)b * DD + tid];
    if (tid < H2) { w3s[tid] = W3[tid]; b2s[tid] = b2[tid]; }
    score[tid] = -INFINITY;
    __syncthreads();   // qs ready

    // ---- fused pass: B = weffT hi/lo + bias1 partials (h fixed per thread) ----
    {
        float bias_part = 0.f;
        for (int idx = tid; idx < DD * H1; idx += NT) {
            int k = idx >> 6;
            int h = idx & 63;
            float qv  = qs[k];
            float w0  = W1[idx];
            float wq  = W1[(size_t)(384 + k) * H1 + h];
            float wc  = W1[(size_t)(576 + k) * H1 + h];
            float wm  = W1[(size_t)(192 + k) * H1 + h];
            float v = w0 + wc + qv * wq;
            __nv_bfloat16 hb = __float2bfloat16_rn(v);
            __nv_bfloat16 lb = __float2bfloat16_rn(v - __bfloat162float(hb));
            uint32_t x  = (uint32_t)(h & 7) << 4;
            uint32_t rb = (uint32_t)h * 768u;
            *reinterpret_cast<__nv_bfloat16*>(smB + rb + (((uint32_t)(2 * k)) ^ x))       = hb;
            *reinterpret_cast<__nv_bfloat16*>(smB + rb + (((uint32_t)(384 + 2 * k)) ^ x)) = lb;
            bias_part = fmaf(qv, wm - wc, bias_part);
        }
        wgt[tid] = bias_part;    // 4 partials per h (threads tid, tid+64, tid+128, tid+192 share h? no:
                                 // thread c*64+h holds partial for h over its 48 k's)
    }
    // ---- W2 b-frags (col-major k16n8, hi/lo) — verified layout ----
    for (int e = tid; e < 512; e += NT) {
        int kb = e >> 7;
        int rem = e & 127;
        int cn = rem >> 5;
        int ln = rem & 31;
        int k0 = kb * 16 + (ln & 3) * 2;
        int col = cn * 8 + (ln >> 2);
        float v00 = W2[(size_t)k0 * H2 + col];
        float v01 = W2[(size_t)(k0 + 1) * H2 + col];
        float v10 = W2[(size_t)(k0 + 8) * H2 + col];
        float v11 = W2[(size_t)(k0 + 9) * H2 + col];
        float h00 = __bfloat162float(__float2bfloat16_rn(v00));
        float h01 = __bfloat162float(__float2bfloat16_rn(v01));
        float h10 = __bfloat162float(__float2bfloat16_rn(v10));
        float h11 = __bfloat162float(__float2bfloat16_rn(v11));
        int basei = (kb * 4 + cn) * 64 + ln * 2;
        w2fh[basei + 0] = pkbf2(v00, v01);
        w2fh[basei + 1] = pkbf2(v10, v11);
        w2fl[basei + 0] = pkbf2(v00 - h00, v01 - h01);
        w2fl[basei + 1] = pkbf2(v10 - h10, v11 - h11);
    }
    // ---- store conv chunk (0,0) ----
    conv_sts(abuf, pf, tid);
    __syncthreads();
    if (tid < H1)
        bias1[tid] = b1[tid] + wgt[tid] + wgt[tid + 64] + wgt[tid + 128] + wgt[tid + 192];
    __syncthreads();   // bias1 done; wgt region now free
    // ---- cache kmask in smem (visible to epilogues via mainloop barriers) ----
    if (tid < SS) kms[tid] = kmask[(size_t)b * SS + tid];

    // ================= main: 2 m-groups x 3 k-chunks, 8 warps n64 =================
    const uint32_t uA = ((uint32_t)(lid >> 4)) * 16u;
    const uint32_t jB = (uint32_t)(lid >> 3);
    const uint32_t uB = (jB & 1u) * 16u;
    const uint32_t xb = ((uint32_t)(lid & 7)) << 4;

    const uint32_t rowA = (uint32_t)(wid * 16 + (lid & 15));
    const uint32_t xa = (rowA & 7u) << 4;
    const uint32_t aB = abase_u32 + rowA * 256u;
    const uint32_t rowB = (jB >> 1) * 8u + (uint32_t)(lid & 7);
    const uint32_t bB0 = bbase_u32 + rowB * 768u;
    const uint32_t bB1 = bB0 + 16u * 768u;
    const uint32_t bB2 = bB0 + 32u * 768u;
    const uint32_t bB3 = bB0 + 48u * 768u;

    for (int g = 0; g < 2; g++) {
        float cc[32];
        #pragma unroll
        for (int j = 0; j < 32; j++) cc[j] = 0.f;

        for (int c = 0; c < 3; c++) {
            const bool has_next = !(g == 1 && c == 2);
            // prefetch next chunk's keys into regs (hidden under GEMM below)
            if (has_next) {
                int ng = (c == 2) ? g + 1 : g;
                int nc = (c == 2) ? 0 : c + 1;
                conv_ldg(pf, kbase, ng * 128, nc * 64, tid);
            }

            // GEMM1 on chunk (g, c): 4 k16 steps, term-major MMA scheduling
            #pragma unroll
            for (int ks = 0; ks < 4; ks++) {
                uint32_t ka_h = (uint32_t)(ks * 32);
                uint32_t ka_l = ka_h + 128u;
                uint32_t kb_h = (uint32_t)(c * 128 + ks * 32);
                uint32_t kb_l = kb_h + 384u;
                uint32_t ah0, ah1, ah2, ah3, al0, al1, al2, al3;
                LDSM4(ah0, ah1, ah2, ah3, aB + ((ka_h + uA) ^ xa));
                LDSM4(al0, al1, al2, al3, aB + ((ka_l + uA) ^ xa));
                uint32_t bh[8], bl[8];
                LDSM4(bh[0], bh[1], bh[2], bh[3], bB0 + ((kb_h + uB) ^ xb));
                LDSM4(bh[4], bh[5], bh[6], bh[7], bB1 + ((kb_h + uB) ^ xb));
                LDSM4(bl[0], bl[1], bl[2], bl[3], bB0 + ((kb_l + uB) ^ xb));
                LDSM4(bl[4], bl[5], bl[6], bl[7], bB1 + ((kb_l + uB) ^ xb));
                #pragma unroll
                for (int gg = 0; gg < 4; gg++)
                    MMA16816(cc[4*gg+0], cc[4*gg+1], cc[4*gg+2], cc[4*gg+3],
                             ah0, ah1, ah2, ah3, bh[2*gg], bh[2*gg+1]);
                #pragma unroll
                for (int gg = 0; gg < 4; gg++)
                    MMA16816(cc[4*gg+0], cc[4*gg+1], cc[4*gg+2], cc[4*gg+3],
                             al0, al1, al2, al3, bh[2*gg], bh[2*gg+1]);
                #pragma unroll
                for (int gg = 0; gg < 4; gg++)
                    MMA16816(cc[4*gg+0], cc[4*gg+1], cc[4*gg+2], cc[4*gg+3],
                             ah0, ah1, ah2, ah3, bl[2*gg], bl[2*gg+1]);
                LDSM4(bh[0], bh[1], bh[2], bh[3], bB2 + ((kb_h + uB) ^ xb));
                LDSM4(bh[4], bh[5], bh[6], bh[7], bB3 + ((kb_h + uB) ^ xb));
                LDSM4(bl[0], bl[1], bl[2], bl[3], bB2 + ((kb_l + uB) ^ xb));
                LDSM4(bl[4], bl[5], bl[6], bl[7], bB3 + ((kb_l + uB) ^ xb));
                #pragma unroll
                for (int gg = 0; gg < 4; gg++)
                    MMA16816(cc[4*(gg+4)+0], cc[4*(gg+4)+1], cc[4*(gg+4)+2], cc[4*(gg+4)+3],
                             ah0, ah1, ah2, ah3, bh[2*gg], bh[2*gg+1]);
                #pragma unroll
                for (int gg = 0; gg < 4; gg++)
                    MMA16816(cc[4*(gg+4)+0], cc[4*(gg+4)+1], cc[4*(gg+4)+2], cc[4*(gg+4)+3],
                             al0, al1, al2, al3, bh[2*gg], bh[2*gg+1]);
                #pragma unroll
                for (int gg = 0; gg < 4; gg++)
                    MMA16816(cc[4*(gg+4)+0], cc[4*(gg+4)+1], cc[4*(gg+4)+2], cc[4*(gg+4)+3],
                             ah0, ah1, ah2, ah3, bl[2*gg], bl[2*gg+1]);
            }
            __syncthreads();       // all warps done reading A-buf chunk (g,c)

            // store next chunk (regs -> A-buf)
            if (has_next) conv_sts(abuf, pf, tid);

            // fused epilogue after the last chunk of this m-group (no A-buf use)
            if (c == 2) {
                #pragma unroll
                for (int j = 0; j < 8; j++) {
                    float2 bb = *reinterpret_cast<const float2*>(bias1 + 8 * j + (lid & 3) * 2);
                    float v0 = cc[4*j+0] + bb.x;
                    float v1 = cc[4*j+1] + bb.y;
                    float v2 = cc[4*j+2] + bb.x;
                    float v3 = cc[4*j+3] + bb.y;
                    cc[4*j+0] = (v0 >= 0.f) ? v0 : a1 * v0;
                    cc[4*j+1] = (v1 >= 0.f) ? v1 : a1 * v1;
                    cc[4*j+2] = (v2 >= 0.f) ? v2 : a1 * v2;
                    cc[4*j+3] = (v3 >= 0.f) ? v3 : a1 * v3;
                }
                uint32_t a2h[16], a2l[16];
                #pragma unroll
                for (int kb = 0; kb < 4; kb++) {
                    #pragma unroll
                    for (int pos = 0; pos < 4; pos++) {
                        int j = 2 * kb + (pos >> 1);
                        int r0 = 4 * j + (pos & 1) * 2;
                        float v0 = cc[r0], v1 = cc[r0 + 1];
                        float h0 = __bfloat162float(__float2bfloat16_rn(v0));
                        float h1 = __bfloat162float(__float2bfloat16_rn(v1));
                        a2h[kb * 4 + pos] = pkbf2(v0, v1);
                        a2l[kb * 4 + pos] = pkbf2(v0 - h0, v1 - h1);
                    }
                }
                float d[16];
                #pragma unroll
                for (int j = 0; j < 16; j++) d[j] = 0.f;
                #pragma unroll
                for (int kb = 0; kb < 4; kb++) {
                    uint32_t* ah = a2h + kb * 4;
                    uint32_t* al = a2l + kb * 4;
                    uint2 wh[4], wl[4];
                    #pragma unroll
                    for (int cn = 0; cn < 4; cn++) {
                        wh[cn] = *reinterpret_cast<const uint2*>(w2fh + (kb * 4 + cn) * 64 + lid * 2);
                        wl[cn] = *reinterpret_cast<const uint2*>(w2fl + (kb * 4 + cn) * 64 + lid * 2);
                    }
                    #pragma unroll
                    for (int cn = 0; cn < 4; cn++)
                        MMA16816(d[4*cn+0], d[4*cn+1], d[4*cn+2], d[4*cn+3],
                                 ah[0], ah[1], ah[2], ah[3], wh[cn].x, wh[cn].y);
                    #pragma unroll
                    for (int cn = 0; cn < 4; cn++)
                        MMA16816(d[4*cn+0], d[4*cn+1], d[4*cn+2], d[4*cn+3],
                                 al[0], al[1], al[2], al[3], wh[cn].x, wh[cn].y);
                    #pragma unroll
                    for (int cn = 0; cn < 4; cn++)
                        MMA16816(d[4*cn+0], d[4*cn+1], d[4*cn+2], d[4*cn+3],
                                 ah[0], ah[1], ah[2], ah[3], wl[cn].x, wl[cn].y);
                }
                float p0 = 0.f, p1 = 0.f;
                #pragma unroll
                for (int cn = 0; cn < 4; cn++) {
                    int col = 8 * cn + (lid & 3) * 2;
                    float2 bb = *reinterpret_cast<const float2*>(b2s + col);
                    float2 ww = *reinterpret_cast<const float2*>(w3s + col);
                    float v0 = d[4*cn+0] + bb.x;
                    float v1 = d[4*cn+1] + bb.y;
                    float v2 = d[4*cn+2] + bb.x;
                    float v3 = d[4*cn+3] + bb.y;
                    v0 = (v0 >= 0.f) ? v0 : a2 * v0;
                    v1 = (v1 >= 0.f) ? v1 : a2 * v1;
                    v2 = (v2 >= 0.f) ? v2 : a2 * v2;
                    v3 = (v3 >= 0.f) ? v3 : a2 * v3;
                    p0 = fmaf(v0, ww.x, p0); p0 = fmaf(v1, ww.y, p0);
                    p1 = fmaf(v2, ww.x, p1); p1 = fmaf(v3, ww.y, p1);
                }
                p0 += __shfl_xor_sync(0xffffffffu, p0, 1);
                p0 += __shfl_xor_sync(0xffffffffu, p0, 2);
                p1 += __shfl_xor_sync(0xffffffffu, p1, 1);
                p1 += __shfl_xor_sync(0xffffffffu, p1, 2);
                if ((lid & 3) == 0) {
                    int row0 = g * 128 + wid * 16 + (lid >> 2);
                    int row1 = row0 + 8;
                    if (row0 < SS)
                        score[row0] = kms[row0] ? (p0 + b3) : -INFINITY;
                    if (row1 < SS)
                        score[row1] = kms[row1] ? (p1 + b3) : -INFINITY;
                }
            }
            __syncthreads();       // next chunk in smem / scores visible
        }
    }

    // ---- softmax via warp shuffles ----
    const float myscore = score[tid];
    float v = myscore;
    #pragma unroll
    for (int off = 16; off > 0; off >>= 1)
        v = fmaxf(v, __shfl_xor_sync(0xffffffffu, v, off));
    if (lid == 0) red[wid] = v;
    __syncthreads();
    if (tid < 32) {
        float mv = (tid < 8) ? red[tid] : -INFINITY;
        #pragma unroll
        for (int off = 4; off > 0; off >>= 1)
            mv = fmaxf(mv, __shfl_xor_sync(0xffffffffu, mv, off));
        if (tid == 0) red[32] = mv;
    }
    __syncthreads();
    const float m = red[32];

    float e = 0.f;
    if (tid < SS && m > -INFINITY && myscore > -INFINITY)
        e = expf(myscore - m);
    float es = e;
    #pragma unroll
    for (int off = 16; off > 0; off >>= 1)
        es += __shfl_xor_sync(0xffffffffu, es, off);
    if (lid == 0) red[wid] = es;
    __syncthreads();
    if (tid < 32) {
        float sv = (tid < 8) ? red[tid] : 0.f;
        #pragma unroll
        for (int off = 4; off > 0; off >>= 1)
            sv += __shfl_xor_sync(0xffffffffu, sv, off);
        if (tid == 0) red[32] = (sv > 0.f) ? (1.f / sv) : 0.f;
    }
    __syncthreads();
    const float inv = red[32];

    {
        float wv = e * inv;
        wgt[tid] = wv;                       // overwrites kmask cache (no longer needed)
        if (tid < SS) out[(size_t)BB * DD + (size_t)b * SS + tid] = wv;
    }
    __syncthreads();

    // ---- weighted sum: out[b,d] = sum_s wgt[s]*keys[b,s,d], 4 streams x unroll 10 ----
    if (tid < DD) {
        const float* kb = kbase + tid;
        float acc0 = 0.f, acc1 = 0.f, acc2_ = 0.f, acc3 = 0.f;
        #pragma unroll 10
        for (int si = 0; si < 50; si++) {
            acc0  = fmaf(wgt[si],       kb[(size_t)si * DD],          acc0);
            acc1  = fmaf(wgt[si + 50],  kb[(size_t)(si + 50) * DD],   acc1);
            acc2_ = fmaf(wgt[si + 100], kb[(size_t)(si + 100) * DD],  acc2_);
            acc3  = fmaf(wgt[si + 150], kb[(size_t)(si + 150) * DD],  acc3);
        }
        out[(size_t)b * DD + tid] = (acc0 + acc1) + (acc2_ + acc3);
    }
}

extern "C" void kernel_launch(void* const* d_in, const int* in_sizes, int n_in,
                              void* d_out, int out_size)
{
    const float* query = (const float*)d_in[0];
    const float* keys  = (const float*)d_in[1];
    const int*   mask  = (const int*)  d_in[2];
    const float* W1    = (const float*)d_in[3];
    const float* b1    = (const float*)d_in[4];
    const float* a1    = (const float*)d_in[5];
    const float* W2    = (const float*)d_in[6];
    const float* b2    = (const float*)d_in[7];
    const float* a2    = (const float*)d_in[8];
    const float* W3    = (const float*)d_in[9];
    const float* b3    = (const float*)d_in[10];
    float* out = (float*)d_out;

    static bool attr_set = false;
    if (!attr_set) {
        cudaFuncSetAttribute(rich_attn_kernel,
                             cudaFuncAttributeMaxDynamicSharedMemorySize,
                             SMEM_FLOATS * sizeof(float));
        attr_set = true;
    }

    rich_attn_kernel<<<BB, NT, SMEM_FLOATS * sizeof(float)>>>(
        query, keys, mask, W1, b1, a1, W2, b2, a2, W3, b3, out);
}